// round 1
// baseline (speedup 1.0000x reference)
#include <cuda_runtime.h>
#include <math.h>

#define B_   8
#define CIN  128
#define CK   64
#define CV   64
#define CO   128
#define N_   4096
#define KVCHUNKS 16

// ---------------- scratch (device globals; allocation-free) ----------------
__device__ float g_yq[B_ * CK * N_];     // conv(q) -> bn -> l2norm (in place)
__device__ float g_yk[B_ * CK * N_];     // conv(k) -> bn -> l2norm (in place)
__device__ float g_yv[B_ * CV * N_];     // conv(v)
__device__ float g_WkT[CIN * CK];        // Wk transposed [ci][co]
__device__ float g_WvT[CIN * CV];
__device__ float g_scale[2 * CK];        // BN fused scale (q,k)
__device__ float g_shift[2 * CK];        // BN fused shift (q,k)
__device__ float g_vsum[B_ * CV];        // sum_n v[b,cv,n]
__device__ float g_kvpart[KVCHUNKS * B_ * CK * CV];
__device__ float g_M[B_ * CK * CO];      // KV @ Ww^T
__device__ float g_obias[B_ * CO];       // vsum @ Ww^T + bw

// ---------------- K0: transpose weights ----------------
__global__ void prep_kernel(const float* __restrict__ Wk, const float* __restrict__ Wv) {
    int idx = blockIdx.x * 256 + threadIdx.x;   // 0 .. 16383
    int which = idx >> 13;                      // 0: Wk, 1: Wv
    int r = idx & 8191;
    int ci = r >> 6;
    int co = r & 63;
    float v = which ? Wv[co * CIN + ci] : Wk[co * CIN + ci];
    if (which) g_WvT[ci * 64 + co] = v;
    else       g_WkT[ci * 64 + co] = v;
}

// ---------------- K1: 1x1 conv (3 GEMMs [64x128]@[128x4096]) ----------------
// grid (N/64, B, 3), 256 threads. Tile: 64 co x 64 n, thread tile 4x4.
__global__ __launch_bounds__(256) void conv_kernel(
    const float* __restrict__ xq, const float* __restrict__ xk,
    const float* __restrict__ xv,
    const float* __restrict__ bk, const float* __restrict__ bv)
{
    int which = blockIdx.z;
    const float* x    = (which == 0) ? xq : (which == 1) ? xk : xv;
    const float* WT   = (which == 2) ? g_WvT : g_WkT;
    const float* bias = (which == 2) ? bv : bk;
    float* y          = (which == 0) ? g_yq : (which == 1) ? g_yk : g_yv;

    int b  = blockIdx.y;
    int n0 = blockIdx.x * 64;
    int tid = threadIdx.x;
    int ty = tid >> 4, tx = tid & 15;

    __shared__ float Ws[64][64];   // [ci_k][co]
    __shared__ float Xs[64][64];   // [ci_k][n]

    float acc[4][4] = {};

    for (int s = 0; s < 2; s++) {
        #pragma unroll
        for (int i = 0; i < 16; i++) {
            int idx = tid + i * 256;
            int cik = idx >> 6, nn = idx & 63;
            Xs[cik][nn] = x[((size_t)(b * CIN + s * 64 + cik)) * N_ + n0 + nn];
            Ws[cik][nn] = WT[(s * 64 + cik) * 64 + nn];
        }
        __syncthreads();
        #pragma unroll 16
        for (int ci = 0; ci < 64; ci++) {
            float4 a = *(const float4*)&Ws[ci][ty * 4];
            float4 q = *(const float4*)&Xs[ci][tx * 4];
            acc[0][0] += a.x * q.x; acc[0][1] += a.x * q.y; acc[0][2] += a.x * q.z; acc[0][3] += a.x * q.w;
            acc[1][0] += a.y * q.x; acc[1][1] += a.y * q.y; acc[1][2] += a.y * q.z; acc[1][3] += a.y * q.w;
            acc[2][0] += a.z * q.x; acc[2][1] += a.z * q.y; acc[2][2] += a.z * q.z; acc[2][3] += a.z * q.w;
            acc[3][0] += a.w * q.x; acc[3][1] += a.w * q.y; acc[3][2] += a.w * q.z; acc[3][3] += a.w * q.w;
        }
        __syncthreads();
    }
    #pragma unroll
    for (int j = 0; j < 4; j++) {
        int co = ty * 4 + j;
        float bb = bias[co];
        float4 o = make_float4(acc[j][0] + bb, acc[j][1] + bb, acc[j][2] + bb, acc[j][3] + bb);
        *(float4*)&y[((size_t)(b * 64 + co)) * N_ + n0 + tx * 4] = o;
    }
}

// ---------------- K2: BN batch stats -> fused scale/shift ----------------
// grid 128 (64 channels x {q,k}), 256 threads
__global__ __launch_bounds__(256) void bn_stats_kernel(
    const float* __restrict__ gamma, const float* __restrict__ beta)
{
    int c = blockIdx.x & 63;
    int which = blockIdx.x >> 6;
    const float* y = which ? g_yk : g_yq;
    int tid = threadIdx.x;

    float s = 0.f, ss = 0.f;
    for (int idx = tid; idx < B_ * N_; idx += 256) {
        int b = idx >> 12, n = idx & (N_ - 1);
        float v = y[((size_t)(b * 64 + c)) * N_ + n];
        s += v; ss += v * v;
    }
    #pragma unroll
    for (int o = 16; o; o >>= 1) {
        s  += __shfl_down_sync(0xffffffffu, s, o);
        ss += __shfl_down_sync(0xffffffffu, ss, o);
    }
    __shared__ float rs[8], rss[8];
    int wid = tid >> 5, lane = tid & 31;
    if (lane == 0) { rs[wid] = s; rss[wid] = ss; }
    __syncthreads();
    if (tid == 0) {
        float S = 0.f, SS = 0.f;
        #pragma unroll
        for (int i = 0; i < 8; i++) { S += rs[i]; SS += rss[i]; }
        const float inv = 1.0f / (float)(B_ * N_);
        float mean = S * inv;
        float var  = SS * inv - mean * mean;
        float rstd = rsqrtf(var + 1e-5f);
        float sc = gamma[c] * rstd;
        g_scale[which * 64 + c] = sc;
        g_shift[which * 64 + c] = beta[c] - mean * sc;
    }
}

// ---------------- K2b: vsum[b,cv] = sum_n v ----------------
__global__ __launch_bounds__(128) void vsum_kernel() {
    int bc = blockIdx.x;                 // b*64+cv, 512 blocks
    const float* v = g_yv + (size_t)bc * N_;
    int tid = threadIdx.x;
    float s = 0.f;
    for (int i = tid; i < N_; i += 128) s += v[i];
    #pragma unroll
    for (int o = 16; o; o >>= 1) s += __shfl_down_sync(0xffffffffu, s, o);
    __shared__ float rs[4];
    if ((tid & 31) == 0) rs[tid >> 5] = s;
    __syncthreads();
    if (tid == 0) g_vsum[bc] = rs[0] + rs[1] + rs[2] + rs[3];
}

// ---------------- K3: apply BN + L2-normalize per (b,n) column (in place) ----
// grid (256, 2), 128 threads; each thread owns one column.
__global__ __launch_bounds__(128) void norm_kernel() {
    int which = blockIdx.y;
    float* y = which ? g_yk : g_yq;
    int tid = threadIdx.x;
    __shared__ float sc_s[64], sh_s[64];
    if (tid < 64) {
        sc_s[tid] = g_scale[which * 64 + tid];
        sh_s[tid] = g_shift[which * 64 + tid];
    }
    __syncthreads();
    int col = blockIdx.x * 128 + tid;    // 0 .. 32767
    int b = col >> 12, n = col & (N_ - 1);
    float v[64];
    float ss = 0.f;
    #pragma unroll
    for (int c = 0; c < 64; c++) {
        float t = y[((size_t)(b * 64 + c)) * N_ + n] * sc_s[c] + sh_s[c];
        v[c] = t; ss += t * t;
    }
    float rn = 1.0f / (sqrtf(ss) + 1e-7f);
    #pragma unroll
    for (int c = 0; c < 64; c++)
        y[((size_t)(b * 64 + c)) * N_ + n] = v[c] * rn;
}

// ---------------- K4: KV partials: KV[b] = k_norm[b] @ v[b]^T ----------------
// grid (KVCHUNKS, B), 256 threads. Each block: n-range of 256 (4 x 64 subtiles).
__global__ __launch_bounds__(256) void kv_kernel() {
    int chunk = blockIdx.x, b = blockIdx.y;
    __shared__ float Ks[64][65];
    __shared__ float Vs[64][65];
    int tid = threadIdx.x;
    int ty = tid >> 4, tx = tid & 15;
    float acc[4][4] = {};

    for (int t = 0; t < 4; t++) {
        int n0 = chunk * 256 + t * 64;
        #pragma unroll
        for (int i = 0; i < 16; i++) {
            int idx = tid + i * 256;
            int c = idx >> 6, nn = idx & 63;
            Ks[c][nn] = g_yk[((size_t)(b * 64 + c)) * N_ + n0 + nn];
            Vs[c][nn] = g_yv[((size_t)(b * 64 + c)) * N_ + n0 + nn];
        }
        __syncthreads();
        #pragma unroll 8
        for (int n = 0; n < 64; n++) {
            float kv[4], vv[4];
            #pragma unroll
            for (int j = 0; j < 4; j++) kv[j] = Ks[ty + j * 16][n];
            #pragma unroll
            for (int j = 0; j < 4; j++) vv[j] = Vs[tx + j * 16][n];
            #pragma unroll
            for (int j = 0; j < 4; j++)
                #pragma unroll
                for (int i = 0; i < 4; i++)
                    acc[j][i] += kv[j] * vv[i];
        }
        __syncthreads();
    }
    #pragma unroll
    for (int j = 0; j < 4; j++)
        #pragma unroll
        for (int i = 0; i < 4; i++)
            g_kvpart[(((size_t)chunk * B_ + b) * 64 + ty + j * 16) * 64 + tx + i * 16] = acc[j][i];
}

// ---------------- K5: per-batch M = KV @ Ww^T, obias = vsum@Ww^T + bw --------
// grid B, 256 threads
__global__ __launch_bounds__(256) void m_kernel(
    const float* __restrict__ Ww, const float* __restrict__ bw)
{
    int b = blockIdx.x;
    __shared__ float KVs[64][64];   // 16 KB
    __shared__ float WwT[64][128];  // 32 KB  (total exactly 48 KB)
    int tid = threadIdx.x;

    for (int e = tid; e < 4096; e += 256) {
        float s = 0.f;
        #pragma unroll
        for (int c2 = 0; c2 < KVCHUNKS; c2++)
            s += g_kvpart[((size_t)c2 * B_ + b) * 4096 + e];
        KVs[e >> 6][e & 63] = s;
    }
    for (int e = tid; e < 8192; e += 256) {
        int cv = e >> 7, co = e & 127;
        WwT[cv][co] = Ww[co * CV + cv];
    }
    __syncthreads();

    int co = tid & 127;
    for (int ck = (tid >> 7); ck < 64; ck += 2) {
        float s = 0.f;
        #pragma unroll 8
        for (int cv = 0; cv < 64; cv++) s += KVs[ck][cv] * WwT[cv][co];
        g_M[((size_t)b * 64 + ck) * CO + co] = s;
    }
    if (tid < 128) {
        float s = bw[tid];
        #pragma unroll 8
        for (int cv = 0; cv < 64; cv++) s += g_vsum[b * 64 + cv] * WwT[cv][tid];
        g_obias[b * CO + tid] = s;
    }
}

// ---------------- K6: out[b,co,n] = sum_ck qn[b,ck,n] * M[b,ck,co] + obias ---
// grid (N/64, B), 256 threads. Tile: 128 co x 64 n, thread tile 8x4.
__global__ __launch_bounds__(256) void out_kernel(float* __restrict__ out) {
    int b = blockIdx.y, n0 = blockIdx.x * 64;
    int tid = threadIdx.x;
    int ty = tid >> 4, tx = tid & 15;
    __shared__ float Ms[64][128];   // 32 KB
    __shared__ float Qs[64][64];    // 16 KB

    for (int e = tid; e < 8192; e += 256)
        Ms[e >> 7][e & 127] = g_M[(size_t)b * 8192 + e];
    for (int e = tid; e < 4096; e += 256)
        Qs[e >> 6][e & 63] = g_yq[((size_t)(b * 64 + (e >> 6))) * N_ + n0 + (e & 63)];
    __syncthreads();

    float acc[8][4] = {};
    #pragma unroll 8
    for (int ck = 0; ck < 64; ck++) {
        float4 a0 = *(const float4*)&Ms[ck][ty * 8];
        float4 a1 = *(const float4*)&Ms[ck][ty * 8 + 4];
        float4 q  = *(const float4*)&Qs[ck][tx * 4];
        acc[0][0] += a0.x * q.x; acc[0][1] += a0.x * q.y; acc[0][2] += a0.x * q.z; acc[0][3] += a0.x * q.w;
        acc[1][0] += a0.y * q.x; acc[1][1] += a0.y * q.y; acc[1][2] += a0.y * q.z; acc[1][3] += a0.y * q.w;
        acc[2][0] += a0.z * q.x; acc[2][1] += a0.z * q.y; acc[2][2] += a0.z * q.z; acc[2][3] += a0.z * q.w;
        acc[3][0] += a0.w * q.x; acc[3][1] += a0.w * q.y; acc[3][2] += a0.w * q.z; acc[3][3] += a0.w * q.w;
        acc[4][0] += a1.x * q.x; acc[4][1] += a1.x * q.y; acc[4][2] += a1.x * q.z; acc[4][3] += a1.x * q.w;
        acc[5][0] += a1.y * q.x; acc[5][1] += a1.y * q.y; acc[5][2] += a1.y * q.z; acc[5][3] += a1.y * q.w;
        acc[6][0] += a1.z * q.x; acc[6][1] += a1.z * q.y; acc[6][2] += a1.z * q.z; acc[6][3] += a1.z * q.w;
        acc[7][0] += a1.w * q.x; acc[7][1] += a1.w * q.y; acc[7][2] += a1.w * q.z; acc[7][3] += a1.w * q.w;
    }
    #pragma unroll
    for (int j = 0; j < 8; j++) {
        int co = ty * 8 + j;
        float ob = g_obias[b * CO + co];
        float4 o = make_float4(acc[j][0] + ob, acc[j][1] + ob, acc[j][2] + ob, acc[j][3] + ob);
        *(float4*)&out[((size_t)(b * CO + co)) * N_ + n0 + tx * 4] = o;
    }
}

// ---------------- launch ----------------
extern "C" void kernel_launch(void* const* d_in, const int* in_sizes, int n_in,
                              void* d_out, int out_size) {
    const float* q     = (const float*)d_in[0];
    const float* k     = (const float*)d_in[1];
    const float* v     = (const float*)d_in[2];
    const float* Wk    = (const float*)d_in[3];
    const float* bk    = (const float*)d_in[4];
    const float* gamma = (const float*)d_in[5];
    const float* beta  = (const float*)d_in[6];
    const float* Wv    = (const float*)d_in[7];
    const float* bv    = (const float*)d_in[8];
    const float* Ww    = (const float*)d_in[9];
    const float* bw    = (const float*)d_in[10];
    float* out = (float*)d_out;

    prep_kernel<<<64, 256>>>(Wk, Wv);
    conv_kernel<<<dim3(N_ / 64, B_, 3), 256>>>(q, k, v, bk, bv);
    bn_stats_kernel<<<128, 256>>>(gamma, beta);
    vsum_kernel<<<B_ * CV, 128>>>();
    norm_kernel<<<dim3(256, 2), 128>>>();
    kv_kernel<<<dim3(KVCHUNKS, B_), 256>>>();
    m_kernel<<<B_, 256>>>(Ww, bw);
    out_kernel<<<dim3(N_ / 64, B_), 256>>>(out);
}